// round 5
// baseline (speedup 1.0000x reference)
#include <cuda_runtime.h>
#include <cstdint>

#define NN 100000
#define EE 1600000
#define GG 4096
#define HH 128
#define LL 4
#define NT2 1564                // ceil(100096/64) row-tiles of 64
#define NPAD (NT2 * 64)         // 100096

// ---------------- device scratch (no allocations allowed) ----------------
__device__ int    g_deg[NN];
__device__ int    g_cursor[NN];
__device__ int    g_rowptr[NN + 1];
__device__ int    g_col[EE];
__device__ float  g_wgt[EE];
__device__ float  g_dis[NN];
__device__ float4 g_h[(size_t)NPAD * 32];   // N x 128 as float4 (padded, zero-init)
__device__ float4 g_m[(size_t)NPAD * 32];   // N x 128 as float4 (padded)
__device__ float  g_gsum[GG];
__device__ float  g_gcnt[GG];
__device__ int    g_blocksums[128];
__device__ int    g_blockoffs[128];
__device__ float  g_Wdup[(size_t)LL * 128 * 128 * 2];  // W with each value duplicated (w,w)

#define FMA2(d, a, b) \
    asm("fma.rn.f32x2 %0, %1, %2, %0;" : "+l"(d) : "l"(a), "l"(b))

// ---------------- helpers ----------------
__device__ __forceinline__ float warp_sum(float v) {
#pragma unroll
    for (int o = 16; o; o >>= 1) v += __shfl_xor_sync(0xffffffffu, v, o);
    return v;
}
__device__ __forceinline__ void fma4(float4& acc, float a, const float4& w) {
    acc.x = fmaf(a, w.x, acc.x);
    acc.y = fmaf(a, w.y, acc.y);
    acc.z = fmaf(a, w.z, acc.z);
    acc.w = fmaf(a, w.w, acc.w);
}

// ---------------- setup kernels ----------------
__global__ void zero_kernel() {
    int i = blockIdx.x * blockDim.x + threadIdx.x;
    if (i < NN) { g_deg[i] = 0; g_cursor[i] = 0; }
    if (i < GG) { g_gsum[i] = 0.f; g_gcnt[i] = 0.f; }
}

__global__ void count_kernel(const int* __restrict__ dst) {
    int e = blockIdx.x * blockDim.x + threadIdx.x;
    if (e < EE) atomicAdd(&g_deg[dst[e]], 1);
}

__global__ void dis_kernel() {
    int i = blockIdx.x * blockDim.x + threadIdx.x;
    if (i < NN) g_dis[i] = rsqrtf((float)(g_deg[i] + 1));
}

__global__ void scan1_kernel() {
    __shared__ int sh[1024];
    int tid = threadIdx.x;
    int idx = blockIdx.x * 1024 + tid;
    int v = (idx < NN) ? g_deg[idx] : 0;
    sh[tid] = v;
    __syncthreads();
#pragma unroll
    for (int off = 1; off < 1024; off <<= 1) {
        int t = (tid >= off) ? sh[tid - off] : 0;
        __syncthreads();
        sh[tid] += t;
        __syncthreads();
    }
    if (idx < NN) g_rowptr[idx] = sh[tid] - v;
    if (tid == 1023) g_blocksums[blockIdx.x] = sh[1023];
}

__global__ void scan2_kernel(int nblocks) {
    __shared__ int sh[128];
    int tid = threadIdx.x;
    int v = (tid < nblocks) ? g_blocksums[tid] : 0;
    sh[tid] = v;
    __syncthreads();
#pragma unroll
    for (int off = 1; off < 128; off <<= 1) {
        int t = (tid >= off) ? sh[tid - off] : 0;
        __syncthreads();
        sh[tid] += t;
        __syncthreads();
    }
    if (tid < nblocks) g_blockoffs[tid] = sh[tid] - v;
    if (tid == 0) g_rowptr[NN] = EE;
}

__global__ void scan3_kernel() {
    int idx = blockIdx.x * 1024 + threadIdx.x;
    if (idx < NN) g_rowptr[idx] += g_blockoffs[blockIdx.x];
}

__global__ void fill_kernel(const int* __restrict__ src, const int* __restrict__ dst) {
    int e = blockIdx.x * blockDim.x + threadIdx.x;
    if (e >= EE) return;
    int s = src[e];
    int d = dst[e];
    int pos = g_rowptr[d] + atomicAdd(&g_cursor[d], 1);
    g_col[pos] = s;
    g_wgt[pos] = g_dis[s] * g_dis[d];
}

// ---------------- W prep: duplicate each value (w,w) for f32x2 ----------------
__global__ void prep_kernel(const float* __restrict__ Wgnn) {
    int idx = blockIdx.x * 256 + threadIdx.x;    // LL*128*128 = 65536
    if (idx >= LL * 128 * 128) return;
    float w = Wgnn[idx];
    g_Wdup[(size_t)idx * 2]     = w;
    g_Wdup[(size_t)idx * 2 + 1] = w;
}

// ---------------- embed: h = relu(x @ W_embed + b_embed) ----------------
__global__ void __launch_bounds__(256) embed_kernel(const float* __restrict__ x,
                                                    const float* __restrict__ We,
                                                    const float* __restrict__ be) {
    __shared__ __align__(16) float sW[11 * HH];
    for (int i = threadIdx.x; i < 11 * HH; i += 256) sW[i] = We[i];
    __syncthreads();
    int warp = threadIdx.x >> 5, lane = threadIdx.x & 31;
    int n = blockIdx.x * 8 + warp;
    if (n >= NN) return;
    float xv = (lane < 11) ? x[(size_t)n * 11 + lane] : 0.f;
    float4 acc = ((const float4*)be)[lane];
    const float4* sWv = (const float4*)sW;
#pragma unroll
    for (int k = 0; k < 11; k++) {
        float a = __shfl_sync(0xffffffffu, xv, k);
        fma4(acc, a, sWv[k * 32 + lane]);
    }
    acc.x = fmaxf(acc.x, 0.f); acc.y = fmaxf(acc.y, 0.f);
    acc.z = fmaxf(acc.z, 0.f); acc.w = fmaxf(acc.w, 0.f);
    g_h[(size_t)n * 32 + lane] = acc;
}

// ---------------- f32x2 GEMM: g_m = g_h @ W ----------------
// Tile: 64 rows x 128 cols per 256-thread block. K in 4 chunks of 32.
// Accumulators pack TWO ROWS per 64-bit reg; A row-pairs pre-packed in a
// transposed smem tile (stride 68 floats to dodge bank conflicts); W in
// duplicated (w,w) form from g_Wdup.
#define SA_STRIDE 68            // floats per k-row (17 ull2, 16B aligned)
__global__ void __launch_bounds__(256) gemm_f2_kernel(int layer) {
    __shared__ __align__(16) float sW[32 * 256];        // 32 KB
    __shared__ __align__(16) float sA[32 * SA_STRIDE];  // 8.5 KB
    int tid = threadIdx.x;
    int warp = tid >> 5, lane = tid & 31;
    int rg = warp >> 1;         // row group 0..3 (rows 16*rg..16*rg+15)
    int ch = warp & 1;          // column half 0..1 (cols 64*ch..64*ch+63)
    size_t rowbase = (size_t)blockIdx.x * 64;

    const float4* Wg = (const float4*)(g_Wdup + (size_t)layer * 32768);
    const float4* hbase = (const float4*)&g_h[rowbase * 32];

    unsigned long long acc[16];
#pragma unroll
    for (int i = 0; i < 16; i++) acc[i] = 0ull;

    for (int kc = 0; kc < 4; kc++) {
        if (kc) __syncthreads();
        float4* sWv = (float4*)sW;
#pragma unroll
        for (int i = tid; i < 2048; i += 256) sWv[i] = Wg[kc * 2048 + i];
        // A transpose: g_h rows [rowbase..+64), k chunk -> sA[k][pair packed]
#pragma unroll
        for (int i = tid; i < 512; i += 256) {
            int r = i >> 3, q = i & 7;
            float4 v = hbase[r * 32 + kc * 8 + q];
            int p2 = r;  // pair index*2 + half == row index within tile
            sA[(4 * q + 0) * SA_STRIDE + p2] = v.x;
            sA[(4 * q + 1) * SA_STRIDE + p2] = v.y;
            sA[(4 * q + 2) * SA_STRIDE + p2] = v.z;
            sA[(4 * q + 3) * SA_STRIDE + p2] = v.w;
        }
        __syncthreads();

        const ulonglong2* sAv = (const ulonglong2*)sA;
        const ulonglong2* sWd = (const ulonglong2*)sW;
#pragma unroll 4
        for (int k = 0; k < 32; k++) {
            ulonglong2 a01 = sAv[k * 17 + rg * 4 + 0];
            ulonglong2 a23 = sAv[k * 17 + rg * 4 + 1];
            ulonglong2 a45 = sAv[k * 17 + rg * 4 + 2];
            ulonglong2 a67 = sAv[k * 17 + rg * 4 + 3];
            ulonglong2 wv  = sWd[k * 64 + 32 * ch + lane];
            FMA2(acc[0],  a01.x, wv.x); FMA2(acc[1],  a01.x, wv.y);
            FMA2(acc[2],  a01.y, wv.x); FMA2(acc[3],  a01.y, wv.y);
            FMA2(acc[4],  a23.x, wv.x); FMA2(acc[5],  a23.x, wv.y);
            FMA2(acc[6],  a23.y, wv.x); FMA2(acc[7],  a23.y, wv.y);
            FMA2(acc[8],  a45.x, wv.x); FMA2(acc[9],  a45.x, wv.y);
            FMA2(acc[10], a45.y, wv.x); FMA2(acc[11], a45.y, wv.y);
            FMA2(acc[12], a67.x, wv.x); FMA2(acc[13], a67.x, wv.y);
            FMA2(acc[14], a67.y, wv.x); FMA2(acc[15], a67.y, wv.y);
        }
    }

    float* mf = (float*)g_m;
    int col = ch * 64 + 2 * lane;
#pragma unroll
    for (int j = 0; j < 8; j++) {
        size_t row0 = rowbase + rg * 16 + 2 * j;
        unsigned long long c0 = acc[2 * j], c1 = acc[2 * j + 1];
        float2 v0 = make_float2(__uint_as_float((uint32_t)c0),
                                __uint_as_float((uint32_t)c1));
        float2 v1 = make_float2(__uint_as_float((uint32_t)(c0 >> 32)),
                                __uint_as_float((uint32_t)(c1 >> 32)));
        *(float2*)(mf + row0 * 128 + col)       = v0;
        *(float2*)(mf + (row0 + 1) * 128 + col) = v1;
    }
}

// ---------------- fused aggregate + bias + LN + relu + residual ----------------
__global__ void __launch_bounds__(256) agg_kernel(const float* __restrict__ b,
                                                  const float* __restrict__ gam,
                                                  const float* __restrict__ bet) {
    int warp = threadIdx.x >> 5, lane = threadIdx.x & 31;
    int n = blockIdx.x * 8 + warp;
    if (n >= NN) return;

    float dn = g_dis[n];
    float4 acc = g_m[(size_t)n * 32 + lane];
    float sn = dn * dn;
    acc.x *= sn; acc.y *= sn; acc.z *= sn; acc.w *= sn;

    int beg = g_rowptr[n], end = g_rowptr[n + 1];
    int e = beg;
    for (; e + 2 <= end; e += 2) {
        int s0 = g_col[e],   s1 = g_col[e + 1];
        float w0 = g_wgt[e], w1 = g_wgt[e + 1];
        float4 v0 = g_m[(size_t)s0 * 32 + lane];
        float4 v1 = g_m[(size_t)s1 * 32 + lane];
        fma4(acc, w0, v0);
        fma4(acc, w1, v1);
    }
    if (e < end) {
        int s = g_col[e];
        float w = g_wgt[e];
        fma4(acc, w, g_m[(size_t)s * 32 + lane]);
    }
    float4 bb = ((const float4*)b)[lane];
    acc.x += bb.x; acc.y += bb.y; acc.z += bb.z; acc.w += bb.w;

    float mu = warp_sum(acc.x + acc.y + acc.z + acc.w) * (1.f / 128.f);
    float4 d = make_float4(acc.x - mu, acc.y - mu, acc.z - mu, acc.w - mu);
    float var = warp_sum(d.x * d.x + d.y * d.y + d.z * d.z + d.w * d.w) * (1.f / 128.f);
    float inv = rsqrtf(var + 1e-5f);

    float4 gg = ((const float4*)gam)[lane];
    float4 bt = ((const float4*)bet)[lane];
    float4 hv = g_h[(size_t)n * 32 + lane];
    float4 o;
    o.x = fmaxf(d.x * inv * gg.x + bt.x, 0.f) + hv.x;
    o.y = fmaxf(d.y * inv * gg.y + bt.y, 0.f) + hv.y;
    o.z = fmaxf(d.z * inv * gg.z + bt.z, 0.f) + hv.z;
    o.w = fmaxf(d.w * inv * gg.w + bt.w, 0.f) + hv.w;
    g_h[(size_t)n * 32 + lane] = o;
}

// ---------------- pooling ----------------
__global__ void __launch_bounds__(256) pool_kernel(const int* __restrict__ batch,
                                                   const float* __restrict__ Wout) {
    int warp = threadIdx.x >> 5, lane = threadIdx.x & 31;
    int n = blockIdx.x * 8 + warp;
    if (n >= NN) return;
    float4 hv = g_h[(size_t)n * 32 + lane];
    float4 wv = ((const float4*)Wout)[lane];
    float p = warp_sum(hv.x * wv.x + hv.y * wv.y + hv.z * wv.z + hv.w * wv.w);
    if (lane == 0) {
        int gidx = batch[n];
        atomicAdd(&g_gsum[gidx], p);
        atomicAdd(&g_gcnt[gidx], 1.f);
    }
}

__global__ void out_kernel(float* __restrict__ out, const float* __restrict__ bout) {
    int gidx = blockIdx.x * blockDim.x + threadIdx.x;
    if (gidx < GG)
        out[gidx] = g_gsum[gidx] / fmaxf(g_gcnt[gidx], 1.f) + bout[0];
}

// ---------------- launch ----------------
extern "C" void kernel_launch(void* const* d_in, const int* in_sizes, int n_in,
                              void* d_out, int out_size) {
    const float* x      = (const float*)d_in[0];
    const int*   eidx   = (const int*)d_in[1];    // int32 (JAX x64 disabled)
    const int*   batch  = (const int*)d_in[2];    // int32
    const float* Wemb   = (const float*)d_in[3];
    const float* bemb   = (const float*)d_in[4];
    const float* Wgnn   = (const float*)d_in[5];
    const float* bgnn   = (const float*)d_in[6];
    const float* gamma  = (const float*)d_in[7];
    const float* beta   = (const float*)d_in[8];
    const float* Wout   = (const float*)d_in[9];
    const float* bout   = (const float*)d_in[10];
    float* out = (float*)d_out;

    const int* src = eidx;
    const int* dst = eidx + EE;

    int nb_scan = (NN + 1023) / 1024;  // 98

    zero_kernel<<<(NN + 255) / 256, 256>>>();
    count_kernel<<<(EE + 255) / 256, 256>>>(dst);
    prep_kernel<<<256, 256>>>(Wgnn);
    dis_kernel<<<(NN + 255) / 256, 256>>>();
    scan1_kernel<<<nb_scan, 1024>>>();
    scan2_kernel<<<1, 128>>>(nb_scan);
    scan3_kernel<<<nb_scan, 1024>>>();
    fill_kernel<<<(EE + 255) / 256, 256>>>(src, dst);

    embed_kernel<<<NN / 8, 256>>>(x, Wemb, bemb);

    for (int l = 0; l < LL; l++) {
        gemm_f2_kernel<<<NT2, 256>>>(l);
        agg_kernel<<<NN / 8, 256>>>(bgnn + l * HH, gamma + l * HH, beta + l * HH);
    }

    pool_kernel<<<NN / 8, 256>>>(batch, Wout);
    out_kernel<<<(GG + 255) / 256, 256>>>(out, bout);
}

// round 6
// speedup vs baseline: 1.2090x; 1.2090x over previous
#include <cuda_runtime.h>
#include <cstdint>

#define NN 100000
#define EE 1600000
#define GG 4096
#define HH 128
#define LL 4
#define NT 782                  // ceil(100000/128) row-tiles of 128
#define NPAD (NT * 128)         // 100096

// ---------------- device scratch (no allocations allowed) ----------------
__device__ int    g_deg[NN];
__device__ int    g_cursor[NN];
__device__ int    g_rowptr[NN + 1];
__device__ int    g_col[EE];
__device__ float  g_wgt[EE];
__device__ float  g_dis[NN];
__device__ float4 g_h[(size_t)NPAD * 32];   // N x 128 as float4 (padded, zero-init)
__device__ float4 g_m[(size_t)NPAD * 32];   // N x 128 as float4 (padded)
__device__ float  g_gsum[GG];
__device__ float  g_gcnt[GG];
__device__ int    g_blocksums[128];
__device__ int    g_blockoffs[128];
// W in mma-fragment layout, tf32 hi/lo: [L][p][kstep 16][ntile 16][r 2][lane 32]
__device__ uint32_t g_Bfrag[LL][2][16][16][2][32];

// ---------------- helpers ----------------
__device__ __forceinline__ float warp_sum(float v) {
#pragma unroll
    for (int o = 16; o; o >>= 1) v += __shfl_xor_sync(0xffffffffu, v, o);
    return v;
}
__device__ __forceinline__ void fma4(float4& acc, float a, const float4& w) {
    acc.x = fmaf(a, w.x, acc.x);
    acc.y = fmaf(a, w.y, acc.y);
    acc.z = fmaf(a, w.z, acc.z);
    acc.w = fmaf(a, w.w, acc.w);
}
__device__ __forceinline__ uint32_t to_tf32(float v) {
    uint32_t r;
    asm("cvt.rna.tf32.f32 %0, %1;" : "=r"(r) : "f"(v));
    return r;
}
__device__ __forceinline__ void mma_tf32(float* d, uint32_t a0, uint32_t a1,
                                         uint32_t a2, uint32_t a3,
                                         uint32_t b0, uint32_t b1) {
    asm("mma.sync.aligned.m16n8k8.row.col.f32.tf32.tf32.f32 "
        "{%0,%1,%2,%3},{%4,%5,%6,%7},{%8,%9},{%0,%1,%2,%3};"
        : "+f"(d[0]), "+f"(d[1]), "+f"(d[2]), "+f"(d[3])
        : "r"(a0), "r"(a1), "r"(a2), "r"(a3), "r"(b0), "r"(b1));
}

// ---------------- setup kernels ----------------
__global__ void zero_kernel() {
    int i = blockIdx.x * blockDim.x + threadIdx.x;
    if (i < NN) { g_deg[i] = 0; g_cursor[i] = 0; }
    if (i < GG) { g_gsum[i] = 0.f; g_gcnt[i] = 0.f; }
}

__global__ void count_kernel(const int* __restrict__ dst) {
    int e = blockIdx.x * blockDim.x + threadIdx.x;
    if (e < EE) atomicAdd(&g_deg[dst[e]], 1);
}

__global__ void dis_kernel() {
    int i = blockIdx.x * blockDim.x + threadIdx.x;
    if (i < NN) g_dis[i] = rsqrtf((float)(g_deg[i] + 1));
}

__global__ void scan1_kernel() {
    __shared__ int sh[1024];
    int tid = threadIdx.x;
    int idx = blockIdx.x * 1024 + tid;
    int v = (idx < NN) ? g_deg[idx] : 0;
    sh[tid] = v;
    __syncthreads();
#pragma unroll
    for (int off = 1; off < 1024; off <<= 1) {
        int t = (tid >= off) ? sh[tid - off] : 0;
        __syncthreads();
        sh[tid] += t;
        __syncthreads();
    }
    if (idx < NN) g_rowptr[idx] = sh[tid] - v;
    if (tid == 1023) g_blocksums[blockIdx.x] = sh[1023];
}

__global__ void scan2_kernel(int nblocks) {
    __shared__ int sh[128];
    int tid = threadIdx.x;
    int v = (tid < nblocks) ? g_blocksums[tid] : 0;
    sh[tid] = v;
    __syncthreads();
#pragma unroll
    for (int off = 1; off < 128; off <<= 1) {
        int t = (tid >= off) ? sh[tid - off] : 0;
        __syncthreads();
        sh[tid] += t;
        __syncthreads();
    }
    if (tid < nblocks) g_blockoffs[tid] = sh[tid] - v;
    if (tid == 0) g_rowptr[NN] = EE;
}

__global__ void scan3_kernel() {
    int idx = blockIdx.x * 1024 + threadIdx.x;
    if (idx < NN) g_rowptr[idx] += g_blockoffs[blockIdx.x];
}

__global__ void fill_kernel(const int* __restrict__ src, const int* __restrict__ dst) {
    int e = blockIdx.x * blockDim.x + threadIdx.x;
    if (e >= EE) return;
    int s = src[e];
    int d = dst[e];
    int pos = g_rowptr[d] + atomicAdd(&g_cursor[d], 1);
    g_col[pos] = s;
    g_wgt[pos] = g_dis[s] * g_dis[d];
}

// ---------------- W prep: tf32 hi/lo split into mma fragment layout ------------
// b0 holds W[k=ks*8 + lane%4][n=nt*8 + lane/4]; b1 is k+4.
__global__ void prep_kernel(const float* __restrict__ Wgnn) {
    int idx = blockIdx.x * 256 + threadIdx.x;    // LL*16*16*2*32 = 65536
    if (idx >= LL * 16 * 16 * 2 * 32) return;
    int lane = idx & 31;
    int r    = (idx >> 5) & 1;
    int nt   = (idx >> 6) & 15;
    int ks   = (idx >> 10) & 15;
    int l    = idx >> 14;
    int k = ks * 8 + r * 4 + (lane & 3);
    int n = nt * 8 + (lane >> 2);
    float w = Wgnn[(size_t)l * 16384 + k * 128 + n];
    uint32_t hi = to_tf32(w);
    float lof = w - __uint_as_float(hi);
    uint32_t lo = to_tf32(lof);
    g_Bfrag[l][0][ks][nt][r][lane] = hi;
    g_Bfrag[l][1][ks][nt][r][lane] = lo;
}

// ---------------- embed: h = relu(x @ W_embed + b_embed) ----------------
__global__ void __launch_bounds__(256) embed_kernel(const float* __restrict__ x,
                                                    const float* __restrict__ We,
                                                    const float* __restrict__ be) {
    __shared__ __align__(16) float sW[11 * HH];
    for (int i = threadIdx.x; i < 11 * HH; i += 256) sW[i] = We[i];
    __syncthreads();
    int warp = threadIdx.x >> 5, lane = threadIdx.x & 31;
    int n = blockIdx.x * 8 + warp;
    if (n >= NN) return;
    float xv = (lane < 11) ? x[(size_t)n * 11 + lane] : 0.f;
    float4 acc = ((const float4*)be)[lane];
    const float4* sWv = (const float4*)sW;
#pragma unroll
    for (int k = 0; k < 11; k++) {
        float a = __shfl_sync(0xffffffffu, xv, k);
        fma4(acc, a, sWv[k * 32 + lane]);
    }
    acc.x = fmaxf(acc.x, 0.f); acc.y = fmaxf(acc.y, 0.f);
    acc.z = fmaxf(acc.z, 0.f); acc.w = fmaxf(acc.w, 0.f);
    g_h[(size_t)n * 32 + lane] = acc;
}

// ---------------- mma.sync tf32 GEMM: g_m = g_h @ W -------------------------
// Block: 256 thr = 8 warps as 4(m) x 2(n). Tile 128 rows x 128 cols.
// Warp: 32 rows (2 x m16) x 64 cols (8 x n8). K: 8 chunks of 16 (2 ksteps).
// 3-pass tf32 split: ah*bh + ah*bl + al*bh.
#define SA_STRIDE 20   // floats per row (16 + 4 pad): conflict-free frag reads
__global__ void __launch_bounds__(256) gemm_mma_kernel(int layer) {
    __shared__ __align__(16) uint32_t sB[2][2][16][2][32]; // [p][ks][nt][r][lane] 16KB
    __shared__ __align__(16) float sA[128 * SA_STRIDE];    // 10KB

    int tid = threadIdx.x;
    int warp = tid >> 5, lane = tid & 31;
    int wm = warp >> 1;            // 0..3  (rows wm*32 .. +32)
    int wn = warp & 1;             // 0..1  (cols wn*64 .. +64)
    int g = lane >> 2, t = lane & 3;
    size_t rowbase = (size_t)blockIdx.x * 128;

    const float4* hbase = (const float4*)&g_h[rowbase * 32];
    const uint32_t* bsrc = &g_Bfrag[layer][0][0][0][0][0];

    float d[2][8][4];
#pragma unroll
    for (int mt = 0; mt < 2; mt++)
#pragma unroll
        for (int nt = 0; nt < 8; nt++)
#pragma unroll
            for (int j = 0; j < 4; j++) d[mt][nt][j] = 0.f;

    for (int c = 0; c < 8; c++) {
        if (c) __syncthreads();
        // B chunk: ksteps 2c, 2c+1, both p. 4 contiguous 1024-float segments.
        {
            float4* dst = (float4*)sB;
#pragma unroll
            for (int p = 0; p < 2; p++)
#pragma unroll
                for (int ks = 0; ks < 2; ks++) {
                    const float4* src = (const float4*)(bsrc + ((size_t)p * 16 + (2 * c + ks)) * 1024);
                    float4* dd = dst + (p * 2 + ks) * 256;
                    if (tid < 256) dd[tid] = src[tid];
                }
        }
        // A chunk: 128 rows x 16 k (float4 q=0..3) into stride-20 smem
#pragma unroll
        for (int i = tid; i < 512; i += 256) {
            int r = i >> 2, q = i & 3;
            ((float4*)sA)[r * 5 + q] = hbase[r * 32 + c * 4 + q];
        }
        __syncthreads();

#pragma unroll
        for (int ks = 0; ks < 2; ks++) {
            // A fragments (hi/lo) for both m-tiles
            uint32_t ah[2][4], al[2][4];
#pragma unroll
            for (int mt = 0; mt < 2; mt++) {
                int row = wm * 32 + mt * 16 + g;
                int col = ks * 8 + t;
                float a0 = sA[row * SA_STRIDE + col];
                float a1 = sA[(row + 8) * SA_STRIDE + col];
                float a2 = sA[row * SA_STRIDE + col + 4];
                float a3 = sA[(row + 8) * SA_STRIDE + col + 4];
                ah[mt][0] = to_tf32(a0); al[mt][0] = to_tf32(a0 - __uint_as_float(ah[mt][0]));
                ah[mt][1] = to_tf32(a1); al[mt][1] = to_tf32(a1 - __uint_as_float(ah[mt][1]));
                ah[mt][2] = to_tf32(a2); al[mt][2] = to_tf32(a2 - __uint_as_float(ah[mt][2]));
                ah[mt][3] = to_tf32(a3); al[mt][3] = to_tf32(a3 - __uint_as_float(ah[mt][3]));
            }
#pragma unroll
            for (int nt = 0; nt < 8; nt++) {
                int ntg = wn * 8 + nt;
                uint32_t bh0 = sB[0][ks][ntg][0][lane];
                uint32_t bh1 = sB[0][ks][ntg][1][lane];
                uint32_t bl0 = sB[1][ks][ntg][0][lane];
                uint32_t bl1 = sB[1][ks][ntg][1][lane];
#pragma unroll
                for (int mt = 0; mt < 2; mt++) {
                    mma_tf32(d[mt][nt], ah[mt][0], ah[mt][1], ah[mt][2], ah[mt][3], bh0, bh1);
                    mma_tf32(d[mt][nt], ah[mt][0], ah[mt][1], ah[mt][2], ah[mt][3], bl0, bl1);
                    mma_tf32(d[mt][nt], al[mt][0], al[mt][1], al[mt][2], al[mt][3], bh0, bh1);
                }
            }
        }
    }

    // epilogue
    float* mf = (float*)g_m;
#pragma unroll
    for (int mt = 0; mt < 2; mt++) {
        size_t row = rowbase + wm * 32 + mt * 16 + g;
#pragma unroll
        for (int nt = 0; nt < 8; nt++) {
            int col = wn * 64 + nt * 8 + 2 * t;
            *(float2*)(mf + row * 128 + col)       = make_float2(d[mt][nt][0], d[mt][nt][1]);
            *(float2*)(mf + (row + 8) * 128 + col) = make_float2(d[mt][nt][2], d[mt][nt][3]);
        }
    }
}

// ---------------- fused aggregate + bias + LN + relu + residual ----------------
__global__ void __launch_bounds__(256) agg_kernel(const float* __restrict__ b,
                                                  const float* __restrict__ gam,
                                                  const float* __restrict__ bet) {
    int warp = threadIdx.x >> 5, lane = threadIdx.x & 31;
    int n = blockIdx.x * 8 + warp;
    if (n >= NN) return;

    float dn = g_dis[n];
    float4 acc = g_m[(size_t)n * 32 + lane];
    float sn = dn * dn;
    acc.x *= sn; acc.y *= sn; acc.z *= sn; acc.w *= sn;

    int beg = g_rowptr[n], end = g_rowptr[n + 1];
    int e = beg;
    for (; e + 2 <= end; e += 2) {
        int s0 = g_col[e],   s1 = g_col[e + 1];
        float w0 = g_wgt[e], w1 = g_wgt[e + 1];
        float4 v0 = g_m[(size_t)s0 * 32 + lane];
        float4 v1 = g_m[(size_t)s1 * 32 + lane];
        fma4(acc, w0, v0);
        fma4(acc, w1, v1);
    }
    if (e < end) {
        int s = g_col[e];
        float w = g_wgt[e];
        fma4(acc, w, g_m[(size_t)s * 32 + lane]);
    }
    float4 bb = ((const float4*)b)[lane];
    acc.x += bb.x; acc.y += bb.y; acc.z += bb.z; acc.w += bb.w;

    float mu = warp_sum(acc.x + acc.y + acc.z + acc.w) * (1.f / 128.f);
    float4 dd = make_float4(acc.x - mu, acc.y - mu, acc.z - mu, acc.w - mu);
    float var = warp_sum(dd.x * dd.x + dd.y * dd.y + dd.z * dd.z + dd.w * dd.w) * (1.f / 128.f);
    float inv = rsqrtf(var + 1e-5f);

    float4 gg = ((const float4*)gam)[lane];
    float4 bt = ((const float4*)bet)[lane];
    float4 hv = g_h[(size_t)n * 32 + lane];
    float4 o;
    o.x = fmaxf(dd.x * inv * gg.x + bt.x, 0.f) + hv.x;
    o.y = fmaxf(dd.y * inv * gg.y + bt.y, 0.f) + hv.y;
    o.z = fmaxf(dd.z * inv * gg.z + bt.z, 0.f) + hv.z;
    o.w = fmaxf(dd.w * inv * gg.w + bt.w, 0.f) + hv.w;
    g_h[(size_t)n * 32 + lane] = o;
}

// ---------------- pooling ----------------
__global__ void __launch_bounds__(256) pool_kernel(const int* __restrict__ batch,
                                                   const float* __restrict__ Wout) {
    int warp = threadIdx.x >> 5, lane = threadIdx.x & 31;
    int n = blockIdx.x * 8 + warp;
    if (n >= NN) return;
    float4 hv = g_h[(size_t)n * 32 + lane];
    float4 wv = ((const float4*)Wout)[lane];
    float p = warp_sum(hv.x * wv.x + hv.y * wv.y + hv.z * wv.z + hv.w * wv.w);
    if (lane == 0) {
        int gidx = batch[n];
        atomicAdd(&g_gsum[gidx], p);
        atomicAdd(&g_gcnt[gidx], 1.f);
    }
}

__global__ void out_kernel(float* __restrict__ out, const float* __restrict__ bout) {
    int gidx = blockIdx.x * blockDim.x + threadIdx.x;
    if (gidx < GG)
        out[gidx] = g_gsum[gidx] / fmaxf(g_gcnt[gidx], 1.f) + bout[0];
}

// ---------------- launch ----------------
extern "C" void kernel_launch(void* const* d_in, const int* in_sizes, int n_in,
                              void* d_out, int out_size) {
    const float* x      = (const float*)d_in[0];
    const int*   eidx   = (const int*)d_in[1];    // int32 (JAX x64 disabled)
    const int*   batch  = (const int*)d_in[2];    // int32
    const float* Wemb   = (const float*)d_in[3];
    const float* bemb   = (const float*)d_in[4];
    const float* Wgnn   = (const float*)d_in[5];
    const float* bgnn   = (const float*)d_in[6];
    const float* gamma  = (const float*)d_in[7];
    const float* beta   = (const float*)d_in[8];
    const float* Wout   = (const float*)d_in[9];
    const float* bout   = (const float*)d_in[10];
    float* out = (float*)d_out;

    const int* src = eidx;
    const int* dst = eidx + EE;

    int nb_scan = (NN + 1023) / 1024;  // 98

    zero_kernel<<<(NN + 255) / 256, 256>>>();
    count_kernel<<<(EE + 255) / 256, 256>>>(dst);
    prep_kernel<<<256, 256>>>(Wgnn);
    dis_kernel<<<(NN + 255) / 256, 256>>>();
    scan1_kernel<<<nb_scan, 1024>>>();
    scan2_kernel<<<1, 128>>>(nb_scan);
    scan3_kernel<<<nb_scan, 1024>>>();
    fill_kernel<<<(EE + 255) / 256, 256>>>(src, dst);

    embed_kernel<<<NN / 8, 256>>>(x, Wemb, bemb);

    for (int l = 0; l < LL; l++) {
        gemm_mma_kernel<<<NT, 256>>>(l);
        agg_kernel<<<NN / 8, 256>>>(bgnn + l * HH, gamma + l * HH, beta + l * HH);
    }

    pool_kernel<<<NN / 8, 256>>>(batch, Wout);
    out_kernel<<<(GG + 255) / 256, 256>>>(out, bout);
}

// round 7
// speedup vs baseline: 1.2848x; 1.0627x over previous
#include <cuda_runtime.h>
#include <cuda_fp16.h>
#include <cstdint>

#define NN 100000
#define EE 1600000
#define GG 4096
#define HH 128
#define LL 4
#define NT 782                  // ceil(100000/128) row-tiles of 128
#define NPAD (NT * 128)         // 100096

// ---------------- device scratch (no allocations allowed) ----------------
__device__ int     g_deg[NN];
__device__ int     g_cursor[NN];
__device__ int     g_rowptr[NN + 1];
__device__ int     g_col[EE];
__device__ float   g_wgt[EE];
__device__ float   g_dis[NN];
__device__ float4  g_h[(size_t)NPAD * 32];   // N x 128 fp32 (padded, zero-init)
__device__ __half2 g_m[(size_t)NPAD * 64];   // N x 128 fp16 (padded)
__device__ float   g_gsum[GG];
__device__ float   g_gcnt[GG];
__device__ int     g_blocksums[128];
__device__ int     g_blockoffs[128];
// W in mma-fragment layout, tf32 hi/lo: [L][p][kstep 16][ntile 16][r 2][lane 32]
__device__ uint32_t g_Bfrag[LL][2][16][16][2][32];

// ---------------- helpers ----------------
__device__ __forceinline__ float warp_sum(float v) {
#pragma unroll
    for (int o = 16; o; o >>= 1) v += __shfl_xor_sync(0xffffffffu, v, o);
    return v;
}
__device__ __forceinline__ void fma4(float4& acc, float a, const float4& w) {
    acc.x = fmaf(a, w.x, acc.x);
    acc.y = fmaf(a, w.y, acc.y);
    acc.z = fmaf(a, w.z, acc.z);
    acc.w = fmaf(a, w.w, acc.w);
}
__device__ __forceinline__ void fma_h4(float4& acc, float w, uint2 u) {
    __half2 p0 = *(__half2*)&u.x;
    __half2 p1 = *(__half2*)&u.y;
    float2 f0 = __half22float2(p0);
    float2 f1 = __half22float2(p1);
    acc.x = fmaf(w, f0.x, acc.x);
    acc.y = fmaf(w, f0.y, acc.y);
    acc.z = fmaf(w, f1.x, acc.z);
    acc.w = fmaf(w, f1.y, acc.w);
}
__device__ __forceinline__ uint32_t to_tf32(float v) {
    uint32_t r;
    asm("cvt.rna.tf32.f32 %0, %1;" : "=r"(r) : "f"(v));
    return r;
}
__device__ __forceinline__ void mma_tf32(float* d, uint32_t a0, uint32_t a1,
                                         uint32_t a2, uint32_t a3,
                                         uint32_t b0, uint32_t b1) {
    asm("mma.sync.aligned.m16n8k8.row.col.f32.tf32.tf32.f32 "
        "{%0,%1,%2,%3},{%4,%5,%6,%7},{%8,%9},{%0,%1,%2,%3};"
        : "+f"(d[0]), "+f"(d[1]), "+f"(d[2]), "+f"(d[3])
        : "r"(a0), "r"(a1), "r"(a2), "r"(a3), "r"(b0), "r"(b1));
}

// ---------------- setup kernels ----------------
__global__ void zero_kernel() {
    int i = blockIdx.x * blockDim.x + threadIdx.x;
    if (i < NN) { g_deg[i] = 0; g_cursor[i] = 0; }
    if (i < GG) { g_gsum[i] = 0.f; g_gcnt[i] = 0.f; }
}

__global__ void count_kernel(const int* __restrict__ dst) {
    int e = blockIdx.x * blockDim.x + threadIdx.x;
    if (e < EE) atomicAdd(&g_deg[dst[e]], 1);
}

__global__ void dis_kernel() {
    int i = blockIdx.x * blockDim.x + threadIdx.x;
    if (i < NN) g_dis[i] = rsqrtf((float)(g_deg[i] + 1));
}

__global__ void scan1_kernel() {
    __shared__ int sh[1024];
    int tid = threadIdx.x;
    int idx = blockIdx.x * 1024 + tid;
    int v = (idx < NN) ? g_deg[idx] : 0;
    sh[tid] = v;
    __syncthreads();
#pragma unroll
    for (int off = 1; off < 1024; off <<= 1) {
        int t = (tid >= off) ? sh[tid - off] : 0;
        __syncthreads();
        sh[tid] += t;
        __syncthreads();
    }
    if (idx < NN) g_rowptr[idx] = sh[tid] - v;
    if (tid == 1023) g_blocksums[blockIdx.x] = sh[1023];
}

__global__ void scan2_kernel(int nblocks) {
    __shared__ int sh[128];
    int tid = threadIdx.x;
    int v = (tid < nblocks) ? g_blocksums[tid] : 0;
    sh[tid] = v;
    __syncthreads();
#pragma unroll
    for (int off = 1; off < 128; off <<= 1) {
        int t = (tid >= off) ? sh[tid - off] : 0;
        __syncthreads();
        sh[tid] += t;
        __syncthreads();
    }
    if (tid < nblocks) g_blockoffs[tid] = sh[tid] - v;
    if (tid == 0) g_rowptr[NN] = EE;
}

__global__ void scan3_kernel() {
    int idx = blockIdx.x * 1024 + threadIdx.x;
    if (idx < NN) g_rowptr[idx] += g_blockoffs[blockIdx.x];
}

__global__ void fill_kernel(const int* __restrict__ src, const int* __restrict__ dst) {
    int e = blockIdx.x * blockDim.x + threadIdx.x;
    if (e >= EE) return;
    int s = src[e];
    int d = dst[e];
    int pos = g_rowptr[d] + atomicAdd(&g_cursor[d], 1);
    g_col[pos] = s;
    g_wgt[pos] = g_dis[s] * g_dis[d];
}

// ---------------- W prep: tf32 hi/lo split into mma fragment layout ------------
__global__ void prep_kernel(const float* __restrict__ Wgnn) {
    int idx = blockIdx.x * 256 + threadIdx.x;    // LL*16*16*2*32 = 65536
    if (idx >= LL * 16 * 16 * 2 * 32) return;
    int lane = idx & 31;
    int r    = (idx >> 5) & 1;
    int nt   = (idx >> 6) & 15;
    int ks   = (idx >> 10) & 15;
    int l    = idx >> 14;
    int k = ks * 8 + r * 4 + (lane & 3);
    int n = nt * 8 + (lane >> 2);
    float w = Wgnn[(size_t)l * 16384 + k * 128 + n];
    uint32_t hi = to_tf32(w);
    float lof = w - __uint_as_float(hi);
    uint32_t lo = to_tf32(lof);
    g_Bfrag[l][0][ks][nt][r][lane] = hi;
    g_Bfrag[l][1][ks][nt][r][lane] = lo;
}

// ---------------- embed: h = relu(x @ W_embed + b_embed) ----------------
__global__ void __launch_bounds__(256) embed_kernel(const float* __restrict__ x,
                                                    const float* __restrict__ We,
                                                    const float* __restrict__ be) {
    __shared__ __align__(16) float sW[11 * HH];
    for (int i = threadIdx.x; i < 11 * HH; i += 256) sW[i] = We[i];
    __syncthreads();
    int warp = threadIdx.x >> 5, lane = threadIdx.x & 31;
    int n = blockIdx.x * 8 + warp;
    if (n >= NN) return;
    float xv = (lane < 11) ? x[(size_t)n * 11 + lane] : 0.f;
    float4 acc = ((const float4*)be)[lane];
    const float4* sWv = (const float4*)sW;
#pragma unroll
    for (int k = 0; k < 11; k++) {
        float a = __shfl_sync(0xffffffffu, xv, k);
        fma4(acc, a, sWv[k * 32 + lane]);
    }
    acc.x = fmaxf(acc.x, 0.f); acc.y = fmaxf(acc.y, 0.f);
    acc.z = fmaxf(acc.z, 0.f); acc.w = fmaxf(acc.w, 0.f);
    g_h[(size_t)n * 32 + lane] = acc;
}

// ---------------- mma.sync tf32 GEMM: g_m(half) = g_h @ W -------------------
// Block: 256 thr = 8 warps as 4(m) x 2(n). Tile 128 rows x 128 cols.
// Warp: 32 rows (2 x m16) x 64 cols (8 x n8). K: 8 chunks of 16 (2 ksteps).
// 3-pass tf32 split: ah*bh + ah*bl + al*bh. Epilogue converts to fp16.
#define SA_STRIDE 20   // floats per row (16 + 4 pad): conflict-free frag reads
__global__ void __launch_bounds__(256) gemm_mma_kernel(int layer) {
    __shared__ __align__(16) uint32_t sB[2][2][16][2][32]; // [p][ks][nt][r][lane] 16KB
    __shared__ __align__(16) float sA[128 * SA_STRIDE];    // 10KB

    int tid = threadIdx.x;
    int warp = tid >> 5, lane = tid & 31;
    int wm = warp >> 1;            // 0..3  (rows wm*32 .. +32)
    int wn = warp & 1;             // 0..1  (cols wn*64 .. +64)
    int g = lane >> 2, t = lane & 3;
    size_t rowbase = (size_t)blockIdx.x * 128;

    const float4* hbase = (const float4*)&g_h[rowbase * 32];
    const uint32_t* bsrc = &g_Bfrag[layer][0][0][0][0][0];

    float d[2][8][4];
#pragma unroll
    for (int mt = 0; mt < 2; mt++)
#pragma unroll
        for (int nt = 0; nt < 8; nt++)
#pragma unroll
            for (int j = 0; j < 4; j++) d[mt][nt][j] = 0.f;

    for (int c = 0; c < 8; c++) {
        if (c) __syncthreads();
        {
            float4* dst = (float4*)sB;
#pragma unroll
            for (int p = 0; p < 2; p++)
#pragma unroll
                for (int ks = 0; ks < 2; ks++) {
                    const float4* src = (const float4*)(bsrc + ((size_t)p * 16 + (2 * c + ks)) * 1024);
                    float4* dd = dst + (p * 2 + ks) * 256;
                    if (tid < 256) dd[tid] = src[tid];
                }
        }
#pragma unroll
        for (int i = tid; i < 512; i += 256) {
            int r = i >> 2, q = i & 3;
            ((float4*)sA)[r * 5 + q] = hbase[r * 32 + c * 4 + q];
        }
        __syncthreads();

#pragma unroll
        for (int ks = 0; ks < 2; ks++) {
            uint32_t ah[2][4], al[2][4];
#pragma unroll
            for (int mt = 0; mt < 2; mt++) {
                int row = wm * 32 + mt * 16 + g;
                int col = ks * 8 + t;
                float a0 = sA[row * SA_STRIDE + col];
                float a1 = sA[(row + 8) * SA_STRIDE + col];
                float a2 = sA[row * SA_STRIDE + col + 4];
                float a3 = sA[(row + 8) * SA_STRIDE + col + 4];
                ah[mt][0] = to_tf32(a0); al[mt][0] = to_tf32(a0 - __uint_as_float(ah[mt][0]));
                ah[mt][1] = to_tf32(a1); al[mt][1] = to_tf32(a1 - __uint_as_float(ah[mt][1]));
                ah[mt][2] = to_tf32(a2); al[mt][2] = to_tf32(a2 - __uint_as_float(ah[mt][2]));
                ah[mt][3] = to_tf32(a3); al[mt][3] = to_tf32(a3 - __uint_as_float(ah[mt][3]));
            }
#pragma unroll
            for (int nt = 0; nt < 8; nt++) {
                int ntg = wn * 8 + nt;
                uint32_t bh0 = sB[0][ks][ntg][0][lane];
                uint32_t bh1 = sB[0][ks][ntg][1][lane];
                uint32_t bl0 = sB[1][ks][ntg][0][lane];
                uint32_t bl1 = sB[1][ks][ntg][1][lane];
#pragma unroll
                for (int mt = 0; mt < 2; mt++) {
                    mma_tf32(d[mt][nt], ah[mt][0], ah[mt][1], ah[mt][2], ah[mt][3], bh0, bh1);
                    mma_tf32(d[mt][nt], ah[mt][0], ah[mt][1], ah[mt][2], ah[mt][3], bl0, bl1);
                    mma_tf32(d[mt][nt], al[mt][0], al[mt][1], al[mt][2], al[mt][3], bh0, bh1);
                }
            }
        }
    }

    // epilogue: fp32 accum -> fp16 pairs
#pragma unroll
    for (int mt = 0; mt < 2; mt++) {
        size_t row = rowbase + wm * 32 + mt * 16 + g;
#pragma unroll
        for (int nt = 0; nt < 8; nt++) {
            int colh = wn * 32 + nt * 4 + t;   // half2 index (cols 2t,2t+1 of n8 tile)
            g_m[row * 64 + colh]       = __floats2half2_rn(d[mt][nt][0], d[mt][nt][1]);
            g_m[(row + 8) * 64 + colh] = __floats2half2_rn(d[mt][nt][2], d[mt][nt][3]);
        }
    }
}

// ---------------- fused aggregate + bias + LN + relu + residual ----------------
__global__ void __launch_bounds__(256) agg_kernel(const float* __restrict__ b,
                                                  const float* __restrict__ gam,
                                                  const float* __restrict__ bet) {
    int warp = threadIdx.x >> 5, lane = threadIdx.x & 31;
    int n = blockIdx.x * 8 + warp;
    if (n >= NN) return;

    const uint2* Mv = (const uint2*)g_m;   // 32 x uint2 per row (4 halves each)

    float dn = g_dis[n];
    float4 acc = make_float4(0.f, 0.f, 0.f, 0.f);
    fma_h4(acc, dn * dn, Mv[(size_t)n * 32 + lane]);   // self loop

    int beg = g_rowptr[n], end = g_rowptr[n + 1];
    int e = beg;
    for (; e + 2 <= end; e += 2) {
        int s0 = g_col[e],   s1 = g_col[e + 1];
        float w0 = g_wgt[e], w1 = g_wgt[e + 1];
        uint2 u0 = Mv[(size_t)s0 * 32 + lane];
        uint2 u1 = Mv[(size_t)s1 * 32 + lane];
        fma_h4(acc, w0, u0);
        fma_h4(acc, w1, u1);
    }
    if (e < end) {
        fma_h4(acc, g_wgt[e], Mv[(size_t)g_col[e] * 32 + lane]);
    }
    float4 bb = ((const float4*)b)[lane];
    acc.x += bb.x; acc.y += bb.y; acc.z += bb.z; acc.w += bb.w;

    float mu = warp_sum(acc.x + acc.y + acc.z + acc.w) * (1.f / 128.f);
    float4 dd = make_float4(acc.x - mu, acc.y - mu, acc.z - mu, acc.w - mu);
    float var = warp_sum(dd.x * dd.x + dd.y * dd.y + dd.z * dd.z + dd.w * dd.w) * (1.f / 128.f);
    float inv = rsqrtf(var + 1e-5f);

    float4 gg = ((const float4*)gam)[lane];
    float4 bt = ((const float4*)bet)[lane];
    float4 hv = g_h[(size_t)n * 32 + lane];
    float4 o;
    o.x = fmaxf(dd.x * inv * gg.x + bt.x, 0.f) + hv.x;
    o.y = fmaxf(dd.y * inv * gg.y + bt.y, 0.f) + hv.y;
    o.z = fmaxf(dd.z * inv * gg.z + bt.z, 0.f) + hv.z;
    o.w = fmaxf(dd.w * inv * gg.w + bt.w, 0.f) + hv.w;
    g_h[(size_t)n * 32 + lane] = o;
}

// ---------------- pooling ----------------
__global__ void __launch_bounds__(256) pool_kernel(const int* __restrict__ batch,
                                                   const float* __restrict__ Wout) {
    int warp = threadIdx.x >> 5, lane = threadIdx.x & 31;
    int n = blockIdx.x * 8 + warp;
    if (n >= NN) return;
    float4 hv = g_h[(size_t)n * 32 + lane];
    float4 wv = ((const float4*)Wout)[lane];
    float p = warp_sum(hv.x * wv.x + hv.y * wv.y + hv.z * wv.z + hv.w * wv.w);
    if (lane == 0) {
        int gidx = batch[n];
        atomicAdd(&g_gsum[gidx], p);
        atomicAdd(&g_gcnt[gidx], 1.f);
    }
}

__global__ void out_kernel(float* __restrict__ out, const float* __restrict__ bout) {
    int gidx = blockIdx.x * blockDim.x + threadIdx.x;
    if (gidx < GG)
        out[gidx] = g_gsum[gidx] / fmaxf(g_gcnt[gidx], 1.f) + bout[0];
}

// ---------------- launch ----------------
extern "C" void kernel_launch(void* const* d_in, const int* in_sizes, int n_in,
                              void* d_out, int out_size) {
    const float* x      = (const float*)d_in[0];
    const int*   eidx   = (const int*)d_in[1];    // int32 (JAX x64 disabled)
    const int*   batch  = (const int*)d_in[2];    // int32
    const float* Wemb   = (const float*)d_in[3];
    const float* bemb   = (const float*)d_in[4];
    const float* Wgnn   = (const float*)d_in[5];
    const float* bgnn   = (const float*)d_in[6];
    const float* gamma  = (const float*)d_in[7];
    const float* beta   = (const float*)d_in[8];
    const float* Wout   = (const float*)d_in[9];
    const float* bout   = (const float*)d_in[10];
    float* out = (float*)d_out;

    const int* src = eidx;
    const int* dst = eidx + EE;

    int nb_scan = (NN + 1023) / 1024;  // 98

    zero_kernel<<<(NN + 255) / 256, 256>>>();
    count_kernel<<<(EE + 255) / 256, 256>>>(dst);
    prep_kernel<<<256, 256>>>(Wgnn);
    dis_kernel<<<(NN + 255) / 256, 256>>>();
    scan1_kernel<<<nb_scan, 1024>>>();
    scan2_kernel<<<1, 128>>>(nb_scan);
    scan3_kernel<<<nb_scan, 1024>>>();
    fill_kernel<<<(EE + 255) / 256, 256>>>(src, dst);

    embed_kernel<<<NN / 8, 256>>>(x, Wemb, bemb);

    for (int l = 0; l < LL; l++) {
        gemm_mma_kernel<<<NT, 256>>>(l);
        agg_kernel<<<NN / 8, 256>>>(bgnn + l * HH, gamma + l * HH, beta + l * HH);
    }

    pool_kernel<<<NN / 8, 256>>>(batch, Wout);
    out_kernel<<<(GG + 255) / 256, 256>>>(out, bout);
}

// round 8
// speedup vs baseline: 1.5327x; 1.1929x over previous
#include <cuda_runtime.h>
#include <cuda_fp16.h>
#include <cstdint>

#define NN 100000
#define EE 1600000
#define GG 4096
#define HH 128
#define LL 4
#define NT 782                  // ceil(100000/128) row-tiles of 128
#define NPAD (NT * 128)         // 100096

// ---------------- device scratch (no allocations allowed) ----------------
__device__ int     g_deg[NN];
__device__ int     g_cursor[NN];
__device__ int     g_rowptr[NN + 1];
__device__ uint2   g_cw[EE];                 // (src idx, weight bits) fused
__device__ float   g_dis[NN];
__device__ float4  g_h[(size_t)NPAD * 32];   // N x 128 fp32 (padded, zero-init)
__device__ __half2 g_m[(size_t)NPAD * 64];   // N x 128 fp16 (padded)
__device__ float   g_gsum[GG];
__device__ float   g_gcnt[GG];
__device__ int     g_blocksums[128];
__device__ int     g_blockoffs[128];
// W in m16n8k16 fragment layout, fp16 hi/lo: [L][p][kc 8][nt 16][r 2][lane 32]
__device__ uint32_t g_Bfrag16[LL][2][8][16][2][32];

// ---------------- helpers ----------------
__device__ __forceinline__ float warp_sum(float v) {
#pragma unroll
    for (int o = 16; o; o >>= 1) v += __shfl_xor_sync(0xffffffffu, v, o);
    return v;
}
__device__ __forceinline__ void fma4(float4& acc, float a, const float4& w) {
    acc.x = fmaf(a, w.x, acc.x);
    acc.y = fmaf(a, w.y, acc.y);
    acc.z = fmaf(a, w.z, acc.z);
    acc.w = fmaf(a, w.w, acc.w);
}
__device__ __forceinline__ void fma_h4(float4& acc, float w, uint2 u) {
    __half2 p0 = *(__half2*)&u.x;
    __half2 p1 = *(__half2*)&u.y;
    float2 f0 = __half22float2(p0);
    float2 f1 = __half22float2(p1);
    acc.x = fmaf(w, f0.x, acc.x);
    acc.y = fmaf(w, f0.y, acc.y);
    acc.z = fmaf(w, f1.x, acc.z);
    acc.w = fmaf(w, f1.y, acc.w);
}
// fp16 hi/lo split of a float2, packed as half2 words
__device__ __forceinline__ void split2(float2 v, uint32_t& hi, uint32_t& lo) {
    __half hx = __float2half_rn(v.x), hy = __float2half_rn(v.y);
    __half lx = __float2half_rn(v.x - __half2float(hx));
    __half ly = __float2half_rn(v.y - __half2float(hy));
    __half2 h2 = __halves2half2(hx, hy);
    __half2 l2 = __halves2half2(lx, ly);
    hi = *(uint32_t*)&h2;
    lo = *(uint32_t*)&l2;
}
__device__ __forceinline__ void mma_f16(float* d, uint32_t a0, uint32_t a1,
                                        uint32_t a2, uint32_t a3,
                                        uint32_t b0, uint32_t b1) {
    asm("mma.sync.aligned.m16n8k16.row.col.f32.f16.f16.f32 "
        "{%0,%1,%2,%3},{%4,%5,%6,%7},{%8,%9},{%0,%1,%2,%3};"
        : "+f"(d[0]), "+f"(d[1]), "+f"(d[2]), "+f"(d[3])
        : "r"(a0), "r"(a1), "r"(a2), "r"(a3), "r"(b0), "r"(b1));
}

// ---------------- setup kernels ----------------
__global__ void zero_kernel() {
    int i = blockIdx.x * blockDim.x + threadIdx.x;
    if (i < NN) { g_deg[i] = 0; g_cursor[i] = 0; }
    if (i < GG) { g_gsum[i] = 0.f; g_gcnt[i] = 0.f; }
}

__global__ void count_kernel(const int* __restrict__ dst) {
    int e = blockIdx.x * blockDim.x + threadIdx.x;
    if (e < EE) atomicAdd(&g_deg[dst[e]], 1);
}

__global__ void dis_kernel() {
    int i = blockIdx.x * blockDim.x + threadIdx.x;
    if (i < NN) g_dis[i] = rsqrtf((float)(g_deg[i] + 1));
}

__global__ void scan1_kernel() {
    __shared__ int sh[1024];
    int tid = threadIdx.x;
    int idx = blockIdx.x * 1024 + tid;
    int v = (idx < NN) ? g_deg[idx] : 0;
    sh[tid] = v;
    __syncthreads();
#pragma unroll
    for (int off = 1; off < 1024; off <<= 1) {
        int t = (tid >= off) ? sh[tid - off] : 0;
        __syncthreads();
        sh[tid] += t;
        __syncthreads();
    }
    if (idx < NN) g_rowptr[idx] = sh[tid] - v;
    if (tid == 1023) g_blocksums[blockIdx.x] = sh[1023];
}

__global__ void scan2_kernel(int nblocks) {
    __shared__ int sh[128];
    int tid = threadIdx.x;
    int v = (tid < nblocks) ? g_blocksums[tid] : 0;
    sh[tid] = v;
    __syncthreads();
#pragma unroll
    for (int off = 1; off < 128; off <<= 1) {
        int t = (tid >= off) ? sh[tid - off] : 0;
        __syncthreads();
        sh[tid] += t;
        __syncthreads();
    }
    if (tid < nblocks) g_blockoffs[tid] = sh[tid] - v;
    if (tid == 0) g_rowptr[NN] = EE;
}

__global__ void scan3_kernel() {
    int idx = blockIdx.x * 1024 + threadIdx.x;
    if (idx < NN) g_rowptr[idx] += g_blockoffs[blockIdx.x];
}

__global__ void fill_kernel(const int* __restrict__ src, const int* __restrict__ dst) {
    int e = blockIdx.x * blockDim.x + threadIdx.x;
    if (e >= EE) return;
    int s = src[e];
    int d = dst[e];
    int pos = g_rowptr[d] + atomicAdd(&g_cursor[d], 1);
    g_cw[pos] = make_uint2((unsigned)s, __float_as_uint(g_dis[s] * g_dis[d]));
}

// ---------------- W prep: fp16 hi/lo split into m16n8k16 fragment layout -------
// b0 = {W[k0][n], W[k0+1][n]}, k0 = kc*16 + r*8 + 2t, n = nt*8 + g.
__global__ void prep_kernel(const float* __restrict__ Wgnn) {
    int idx = blockIdx.x * 256 + threadIdx.x;    // LL*2*8*16*2*32 / 2 halves = 65536
    if (idx >= LL * 8 * 16 * 2 * 32) return;     // 32768 per... compute per (l,kc,nt,r,lane)
    int lane = idx & 31;
    int r    = (idx >> 5) & 1;
    int nt   = (idx >> 6) & 15;
    int kc   = (idx >> 10) & 7;
    int l    = idx >> 13;
    int t = lane & 3, g = lane >> 2;
    int k0 = kc * 16 + r * 8 + 2 * t;
    int n  = nt * 8 + g;
    float w0 = Wgnn[(size_t)l * 16384 + k0 * 128 + n];
    float w1 = Wgnn[(size_t)l * 16384 + (k0 + 1) * 128 + n];
    uint32_t hi, lo;
    split2(make_float2(w0, w1), hi, lo);
    g_Bfrag16[l][0][kc][nt][r][lane] = hi;
    g_Bfrag16[l][1][kc][nt][r][lane] = lo;
}

// ---------------- embed: h = relu(x @ W_embed + b_embed) ----------------
__global__ void __launch_bounds__(256) embed_kernel(const float* __restrict__ x,
                                                    const float* __restrict__ We,
                                                    const float* __restrict__ be) {
    __shared__ __align__(16) float sW[11 * HH];
    for (int i = threadIdx.x; i < 11 * HH; i += 256) sW[i] = We[i];
    __syncthreads();
    int warp = threadIdx.x >> 5, lane = threadIdx.x & 31;
    int n = blockIdx.x * 8 + warp;
    if (n >= NN) return;
    float xv = (lane < 11) ? x[(size_t)n * 11 + lane] : 0.f;
    float4 acc = ((const float4*)be)[lane];
    const float4* sWv = (const float4*)sW;
#pragma unroll
    for (int k = 0; k < 11; k++) {
        float a = __shfl_sync(0xffffffffu, xv, k);
        fma4(acc, a, sWv[k * 32 + lane]);
    }
    acc.x = fmaxf(acc.x, 0.f); acc.y = fmaxf(acc.y, 0.f);
    acc.z = fmaxf(acc.z, 0.f); acc.w = fmaxf(acc.w, 0.f);
    g_h[(size_t)n * 32 + lane] = acc;
}

// ---------------- mma.sync fp16 GEMM: g_m(half) = g_h @ W -------------------
// Block: 256 thr = 8 warps as 4(m) x 2(n). Tile 128 rows x 128 cols.
// Warp: 32 rows (2 x m16) x 64 cols (8 x n8). K: 8 chunks of 16 (one k16 step).
// 3-pass fp16 hi/lo split: ah*bh + ah*bl + al*bh (al*bl ~ 2^-22, dropped).
#define SA_STRIDE 20   // floats per row (16 + 4 pad)
__global__ void __launch_bounds__(256) gemm_mma_kernel(int layer) {
    __shared__ __align__(16) uint32_t sB[2][16][2][32];   // [p][nt][r][lane] 8KB
    __shared__ __align__(16) float sA[128 * SA_STRIDE];   // 10KB

    int tid = threadIdx.x;
    int warp = tid >> 5, lane = tid & 31;
    int wm = warp >> 1;            // 0..3  (rows wm*32 .. +32)
    int wn = warp & 1;             // 0..1  (cols wn*64 .. +64)
    int g = lane >> 2, t = lane & 3;
    size_t rowbase = (size_t)blockIdx.x * 128;

    const float4* hbase = (const float4*)&g_h[rowbase * 32];
    const uint32_t* bsrc = &g_Bfrag16[layer][0][0][0][0][0];

    float d[2][8][4];
#pragma unroll
    for (int mt = 0; mt < 2; mt++)
#pragma unroll
        for (int nt = 0; nt < 8; nt++)
#pragma unroll
            for (int j = 0; j < 4; j++) d[mt][nt][j] = 0.f;

    for (int c = 0; c < 8; c++) {
        if (c) __syncthreads();
        // B chunk: p=0 (hi) and p=1 (lo), 1024 uint32 each
#pragma unroll
        for (int p = 0; p < 2; p++) {
            const float4* src = (const float4*)(bsrc + (size_t)p * 8192 + c * 1024);
            ((float4*)sB)[p * 256 + tid] = src[tid];
        }
        // A chunk: 128 rows x 16 k into stride-20 smem
#pragma unroll
        for (int i = tid; i < 512; i += 256) {
            int r = i >> 2, q = i & 3;
            ((float4*)sA)[r * 5 + q] = hbase[r * 32 + c * 4 + q];
        }
        __syncthreads();

        // A fragments (hi/lo) for both m-tiles
        uint32_t ah[2][4], al[2][4];
#pragma unroll
        for (int mt = 0; mt < 2; mt++) {
            int row = wm * 32 + mt * 16 + g;
            float2 x0 = *(float2*)&sA[row * SA_STRIDE + 2 * t];
            float2 x1 = *(float2*)&sA[(row + 8) * SA_STRIDE + 2 * t];
            float2 x2 = *(float2*)&sA[row * SA_STRIDE + 2 * t + 8];
            float2 x3 = *(float2*)&sA[(row + 8) * SA_STRIDE + 2 * t + 8];
            split2(x0, ah[mt][0], al[mt][0]);
            split2(x1, ah[mt][1], al[mt][1]);
            split2(x2, ah[mt][2], al[mt][2]);
            split2(x3, ah[mt][3], al[mt][3]);
        }
#pragma unroll
        for (int nt = 0; nt < 8; nt++) {
            int ntg = wn * 8 + nt;
            uint32_t bh0 = sB[0][ntg][0][lane];
            uint32_t bh1 = sB[0][ntg][1][lane];
            uint32_t bl0 = sB[1][ntg][0][lane];
            uint32_t bl1 = sB[1][ntg][1][lane];
#pragma unroll
            for (int mt = 0; mt < 2; mt++) {
                mma_f16(d[mt][nt], ah[mt][0], ah[mt][1], ah[mt][2], ah[mt][3], bh0, bh1);
                mma_f16(d[mt][nt], ah[mt][0], ah[mt][1], ah[mt][2], ah[mt][3], bl0, bl1);
                mma_f16(d[mt][nt], al[mt][0], al[mt][1], al[mt][2], al[mt][3], bh0, bh1);
            }
        }
    }

    // epilogue: fp32 accum -> fp16 pairs
#pragma unroll
    for (int mt = 0; mt < 2; mt++) {
        size_t row = rowbase + wm * 32 + mt * 16 + g;
#pragma unroll
        for (int nt = 0; nt < 8; nt++) {
            int colh = wn * 32 + nt * 4 + t;   // half2 index
            g_m[row * 64 + colh]       = __floats2half2_rn(d[mt][nt][0], d[mt][nt][1]);
            g_m[(row + 8) * 64 + colh] = __floats2half2_rn(d[mt][nt][2], d[mt][nt][3]);
        }
    }
}

// ---------------- fused aggregate + bias + LN + relu + residual ----------------
__global__ void __launch_bounds__(256) agg_kernel(const float* __restrict__ b,
                                                  const float* __restrict__ gam,
                                                  const float* __restrict__ bet) {
    int warp = threadIdx.x >> 5, lane = threadIdx.x & 31;
    int n = blockIdx.x * 8 + warp;
    if (n >= NN) return;

    const uint2* Mv = (const uint2*)g_m;   // 32 x uint2 per row (4 halves each)

    float dn = g_dis[n];
    float4 acc = make_float4(0.f, 0.f, 0.f, 0.f);
    fma_h4(acc, dn * dn, Mv[(size_t)n * 32 + lane]);   // self loop

    int beg = g_rowptr[n], end = g_rowptr[n + 1];
    int e = beg;
    for (; e + 4 <= end; e += 4) {
        uint2 c0 = g_cw[e],     c1 = g_cw[e + 1];
        uint2 c2 = g_cw[e + 2], c3 = g_cw[e + 3];
        uint2 u0 = Mv[(size_t)c0.x * 32 + lane];
        uint2 u1 = Mv[(size_t)c1.x * 32 + lane];
        uint2 u2 = Mv[(size_t)c2.x * 32 + lane];
        uint2 u3 = Mv[(size_t)c3.x * 32 + lane];
        fma_h4(acc, __uint_as_float(c0.y), u0);
        fma_h4(acc, __uint_as_float(c1.y), u1);
        fma_h4(acc, __uint_as_float(c2.y), u2);
        fma_h4(acc, __uint_as_float(c3.y), u3);
    }
    for (; e < end; e++) {
        uint2 cw = g_cw[e];
        fma_h4(acc, __uint_as_float(cw.y), Mv[(size_t)cw.x * 32 + lane]);
    }
    float4 bb = ((const float4*)b)[lane];
    acc.x += bb.x; acc.y += bb.y; acc.z += bb.z; acc.w += bb.w;

    float mu = warp_sum(acc.x + acc.y + acc.z + acc.w) * (1.f / 128.f);
    float4 dd = make_float4(acc.x - mu, acc.y - mu, acc.z - mu, acc.w - mu);
    float var = warp_sum(dd.x * dd.x + dd.y * dd.y + dd.z * dd.z + dd.w * dd.w) * (1.f / 128.f);
    float inv = rsqrtf(var + 1e-5f);

    float4 gg = ((const float4*)gam)[lane];
    float4 bt = ((const float4*)bet)[lane];
    float4 hv = g_h[(size_t)n * 32 + lane];
    float4 o;
    o.x = fmaxf(dd.x * inv * gg.x + bt.x, 0.f) + hv.x;
    o.y = fmaxf(dd.y * inv * gg.y + bt.y, 0.f) + hv.y;
    o.z = fmaxf(dd.z * inv * gg.z + bt.z, 0.f) + hv.z;
    o.w = fmaxf(dd.w * inv * gg.w + bt.w, 0.f) + hv.w;
    g_h[(size_t)n * 32 + lane] = o;
}

// ---------------- pooling ----------------
__global__ void __launch_bounds__(256) pool_kernel(const int* __restrict__ batch,
                                                   const float* __restrict__ Wout) {
    int warp = threadIdx.x >> 5, lane = threadIdx.x & 31;
    int n = blockIdx.x * 8 + warp;
    if (n >= NN) return;
    float4 hv = g_h[(size_t)n * 32 + lane];
    float4 wv = ((const float4*)Wout)[lane];
    float p = warp_sum(hv.x * wv.x + hv.y * wv.y + hv.z * wv.z + hv.w * wv.w);
    if (lane == 0) {
        int gidx = batch[n];
        atomicAdd(&g_gsum[gidx], p);
        atomicAdd(&g_gcnt[gidx], 1.f);
    }
}

__global__ void out_kernel(float* __restrict__ out, const float* __restrict__ bout) {
    int gidx = blockIdx.x * blockDim.x + threadIdx.x;
    if (gidx < GG)
        out[gidx] = g_gsum[gidx] / fmaxf(g_gcnt[gidx], 1.f) + bout[0];
}

// ---------------- launch ----------------
extern "C" void kernel_launch(void* const* d_in, const int* in_sizes, int n_in,
                              void* d_out, int out_size) {
    const float* x      = (const float*)d_in[0];
    const int*   eidx   = (const int*)d_in[1];    // int32 (JAX x64 disabled)
    const int*   batch  = (const int*)d_in[2];    // int32
    const float* Wemb   = (const float*)d_in[3];
    const float* bemb   = (const float*)d_in[4];
    const float* Wgnn   = (const float*)d_in[5];
    const float* bgnn   = (const float*)d_in[6];
    const float* gamma  = (const float*)d_in[7];
    const float* beta   = (const float*)d_in[8];
    const float* Wout   = (const float*)d_in[9];
    const float* bout   = (const float*)d_in[10];
    float* out = (float*)d_out;

    const int* src = eidx;
    const int* dst = eidx + EE;

    int nb_scan = (NN + 1023) / 1024;  // 98

    zero_kernel<<<(NN + 255) / 256, 256>>>();
    count_kernel<<<(EE + 255) / 256, 256>>>(dst);
    prep_kernel<<<128, 256>>>(Wgnn);
    dis_kernel<<<(NN + 255) / 256, 256>>>();
    scan1_kernel<<<nb_scan, 1024>>>();
    scan2_kernel<<<1, 128>>>(nb_scan);
    scan3_kernel<<<nb_scan, 1024>>>();
    fill_kernel<<<(EE + 255) / 256, 256>>>(src, dst);

    embed_kernel<<<NN / 8, 256>>>(x, Wemb, bemb);

    for (int l = 0; l < LL; l++) {
        gemm_mma_kernel<<<NT, 256>>>(l);
        agg_kernel<<<NN / 8, 256>>>(bgnn + l * HH, gamma + l * HH, beta + l * HH);
    }

    pool_kernel<<<NN / 8, 256>>>(batch, Wout);
    out_kernel<<<(GG + 255) / 256, 256>>>(out, bout);
}